// round 1
// baseline (speedup 1.0000x reference)
#include <cuda_runtime.h>
#include <math.h>

// Problem constants
#define BB 2
#define LL 4096
#define DMOD 1024
#define DI 2048
#define DTR 64
#define KC 4
#define ROWS (BB * LL)   // 8192

// ---------------------------------------------------------------------------
// Scratch (device globals; no allocation allowed)
// ---------------------------------------------------------------------------
__device__ float g_xz[(size_t)ROWS * 2 * DI];  // in_proj output: [row, 0..DI-1]=xi, [DI..2DI-1]=z
__device__ float g_u [(size_t)ROWS * DI];      // conv+silu output (scan input u)
__device__ float g_e [(size_t)ROWS * DI];      // decay factors
__device__ float g_yg[(size_t)ROWS * DI];      // gated scan output

// ---------------------------------------------------------------------------
// SGEMM: C[M,N] = A[M,K] * B[N,K]^T   (both row-major, K mult of 8,
// M mult of 128, N mult of 128 for this problem's shapes)
// 128x128 tile, BK=8, 256 threads, 8x8 per thread, reg-prefetch pipeline.
// ---------------------------------------------------------------------------
#define BM 128
#define BN 128
#define BK 8

__global__ __launch_bounds__(256, 2)
void sgemm_nt(const float* __restrict__ A, const float* __restrict__ B,
              float* __restrict__ C, int M, int N, int K) {
    __shared__ float As[BK][BM];
    __shared__ float Bs[BK][BN];

    const int tid = threadIdx.x;
    const int bx = blockIdx.x;   // N tile
    const int by = blockIdx.y;   // M tile

    const float* Ag = A + (size_t)by * BM * K;
    const float* Bg = B + (size_t)bx * BN * K;

    const int lrow = tid >> 1;          // 0..127
    const int lcol = (tid & 1) * 4;     // 0 or 4

    const int tx = tid & 15;            // 0..15 -> N
    const int ty = tid >> 4;            // 0..15 -> M

    float acc[8][8];
    #pragma unroll
    for (int i = 0; i < 8; i++)
        #pragma unroll
        for (int j = 0; j < 8; j++) acc[i][j] = 0.f;

    const int nK = K / BK;

    float4 aReg = *(const float4*)(Ag + (size_t)lrow * K + lcol);
    float4 bReg = *(const float4*)(Bg + (size_t)lrow * K + lcol);

    for (int kt = 0; kt < nK; ++kt) {
        __syncthreads();
        As[lcol + 0][lrow] = aReg.x;
        As[lcol + 1][lrow] = aReg.y;
        As[lcol + 2][lrow] = aReg.z;
        As[lcol + 3][lrow] = aReg.w;
        Bs[lcol + 0][lrow] = bReg.x;
        Bs[lcol + 1][lrow] = bReg.y;
        Bs[lcol + 2][lrow] = bReg.z;
        Bs[lcol + 3][lrow] = bReg.w;
        __syncthreads();

        if (kt + 1 < nK) {
            aReg = *(const float4*)(Ag + (size_t)lrow * K + (kt + 1) * BK + lcol);
            bReg = *(const float4*)(Bg + (size_t)lrow * K + (kt + 1) * BK + lcol);
        }

        #pragma unroll
        for (int k = 0; k < BK; k++) {
            float a[8], b[8];
            #pragma unroll
            for (int i = 0; i < 8; i++) a[i] = As[k][ty * 8 + i];
            #pragma unroll
            for (int j = 0; j < 8; j++) b[j] = Bs[k][tx * 8 + j];
            #pragma unroll
            for (int i = 0; i < 8; i++)
                #pragma unroll
                for (int j = 0; j < 8; j++)
                    acc[i][j] = fmaf(a[i], b[j], acc[i][j]);
        }
    }

    float* Cg = C + (size_t)(by * BM) * N + bx * BN;
    #pragma unroll
    for (int i = 0; i < 8; i++) {
        #pragma unroll
        for (int j = 0; j < 8; j += 4) {
            float4 v = make_float4(acc[i][j], acc[i][j + 1], acc[i][j + 2], acc[i][j + 3]);
            *(float4*)(Cg + (size_t)(ty * 8 + i) * N + tx * 8 + j) = v;
        }
    }
}

// ---------------------------------------------------------------------------
// Depthwise causal conv1d (K=4) + bias + SiLU.
// Reads xi half of g_xz; writes g_u. One thread per output element.
// ---------------------------------------------------------------------------
__global__ __launch_bounds__(256)
void conv_silu_kernel(const float* __restrict__ xz,
                      const float* __restrict__ cw,
                      const float* __restrict__ cb,
                      float* __restrict__ u) {
    int idx = blockIdx.x * blockDim.x + threadIdx.x;   // < ROWS*DI
    int d  = idx & (DI - 1);
    int bl = idx / DI;          // b*L + l
    int l  = bl & (LL - 1);

    float acc = cb[d];
    #pragma unroll
    for (int k = 0; k < KC; k++) {
        int ls = l - (KC - 1) + k;
        if (ls >= 0) {
            acc = fmaf(cw[d * KC + k],
                       xz[(size_t)(bl - (KC - 1) + k) * (2 * DI) + d], acc);
        }
    }
    float s = acc / (1.f + expf(-acc));   // silu
    u[idx] = s;
}

// ---------------------------------------------------------------------------
// Fused dt path: per row (b,l):
//   dt_low[r] = <u_row, x_proj_w[r,:]>                (DT=64)
//   delta[d]  = clip(softplus(<dt_low, dt_proj_w[d,:]> + b[d]), 1e-6, 10)
//   A[d]      = clip(-exp(A_log[d]), -10, -1e-6)
//   e[d]      = clip(exp(delta*A), 1e-6, 1)
// One block (256 threads) per row.
// ---------------------------------------------------------------------------
__global__ __launch_bounds__(256)
void dt_kernel(const float* __restrict__ u,
               const float* __restrict__ xpw,    // [DT, DI]
               const float* __restrict__ dtw,    // [DI, DT]
               const float* __restrict__ dtb,    // [DI]
               const float* __restrict__ alog,   // [DI]
               float* __restrict__ e) {
    __shared__ float s_x[DI];
    __shared__ float s_dt[DTR];

    const int row = blockIdx.x;
    const int tid = threadIdx.x;
    const float* urow = u + (size_t)row * DI;

    for (int i = tid; i < DI; i += 256) s_x[i] = urow[i];
    __syncthreads();

    // Phase 1: dt_low. 8 warps, 8 r's per warp, 8 accumulators per lane.
    {
        const int wid = tid >> 5, lane = tid & 31;
        float accv[8];
        #pragma unroll
        for (int rr = 0; rr < 8; rr++) accv[rr] = 0.f;
        const int rbase = wid * 8;
        for (int j = 0; j < DI / 32; j++) {
            float xv = s_x[lane + 32 * j];
            #pragma unroll
            for (int rr = 0; rr < 8; rr++)
                accv[rr] = fmaf(xpw[(size_t)(rbase + rr) * DI + lane + 32 * j], xv, accv[rr]);
        }
        #pragma unroll
        for (int rr = 0; rr < 8; rr++) {
            float v = accv[rr];
            #pragma unroll
            for (int off = 16; off > 0; off >>= 1)
                v += __shfl_down_sync(0xFFFFFFFFu, v, off);
            if (lane == 0) s_dt[rbase + rr] = v;
        }
    }
    __syncthreads();

    // Phase 2: dt_proj + softplus + exp. 8 d's per thread.
    #pragma unroll
    for (int i = 0; i < 8; i++) {
        int d = tid + i * 256;
        float acc = dtb[d];
        const float4* wp = (const float4*)(dtw + (size_t)d * DTR);
        #pragma unroll
        for (int r4 = 0; r4 < DTR / 4; r4++) {
            float4 w = wp[r4];
            acc = fmaf(w.x, s_dt[r4 * 4 + 0], acc);
            acc = fmaf(w.y, s_dt[r4 * 4 + 1], acc);
            acc = fmaf(w.z, s_dt[r4 * 4 + 2], acc);
            acc = fmaf(w.w, s_dt[r4 * 4 + 3], acc);
        }
        float delta = (acc > 20.f) ? acc : log1pf(expf(acc));
        delta = fminf(fmaxf(delta, 1e-6f), 10.f);
        float A = -expf(alog[d]);
        A = fminf(fmaxf(A, -10.f), -1e-6f);
        float ev = expf(delta * A);
        ev = fminf(fmaxf(ev, 1e-6f), 1.f);
        e[(size_t)row * DI + d] = ev;
    }
}

// ---------------------------------------------------------------------------
// Selective scan + skip + gate, fused.
//   state = clip(state*e + u, +-1e4)
//   y     = clip(state + u*D, +-1e4)
//   yg    = y * silu(z)
// One thread per (b, d) channel; serial over L with depth-4 load prefetch.
// ---------------------------------------------------------------------------
#define SCAN_PF 4
__global__ __launch_bounds__(128)
void scan_kernel(const float* __restrict__ e,
                 const float* __restrict__ u,
                 const float* __restrict__ xz,   // z half
                 const float* __restrict__ Dvec,
                 float* __restrict__ yg) {
    int gid = blockIdx.x * blockDim.x + threadIdx.x;   // < BB*DI
    int b = gid / DI;
    int d = gid - b * DI;
    const float Dd = Dvec[d];

    float eb[SCAN_PF], ub[SCAN_PF], zb[SCAN_PF];

    size_t base  = (size_t)b * LL * DI + d;       // stride DI per l
    size_t zbase = (size_t)b * LL * (2 * DI) + DI + d;

    #pragma unroll
    for (int p = 0; p < SCAN_PF; p++) {
        eb[p] = e[base + (size_t)p * DI];
        ub[p] = u[base + (size_t)p * DI];
        zb[p] = xz[zbase + (size_t)p * (2 * DI)];
    }

    float state = 0.f;
    #pragma unroll 4
    for (int l = 0; l < LL; l++) {
        int slot = l & (SCAN_PF - 1);
        float et = eb[slot], ut = ub[slot], zt = zb[slot];
        if (l + SCAN_PF < LL) {
            eb[slot] = e[base + (size_t)(l + SCAN_PF) * DI];
            ub[slot] = u[base + (size_t)(l + SCAN_PF) * DI];
            zb[slot] = xz[zbase + (size_t)(l + SCAN_PF) * (2 * DI)];
        }
        state = fminf(fmaxf(fmaf(state, et, ut), -1e4f), 1e4f);
        float y = fminf(fmaxf(fmaf(ut, Dd, state), -1e4f), 1e4f);
        float sg = zt / (1.f + expf(-zt));
        yg[base + (size_t)l * DI] = y * sg;
    }
}

// ---------------------------------------------------------------------------
// Launch
// ---------------------------------------------------------------------------
extern "C" void kernel_launch(void* const* d_in, const int* in_sizes, int n_in,
                              void* d_out, int out_size) {
    const float* x      = (const float*)d_in[0];
    const float* inw    = (const float*)d_in[1];
    const float* convw  = (const float*)d_in[2];
    const float* convb  = (const float*)d_in[3];
    const float* xpw    = (const float*)d_in[4];
    const float* dtw    = (const float*)d_in[5];
    const float* dtb    = (const float*)d_in[6];
    const float* alog   = (const float*)d_in[7];
    const float* Dvec   = (const float*)d_in[8];
    const float* outw   = (const float*)d_in[9];
    float* out = (float*)d_out;

    float *xz, *u, *e, *yg;
    cudaGetSymbolAddress((void**)&xz, g_xz);
    cudaGetSymbolAddress((void**)&u,  g_u);
    cudaGetSymbolAddress((void**)&e,  g_e);
    cudaGetSymbolAddress((void**)&yg, g_yg);

    // 1. in_proj: xz[8192, 4096] = x[8192,1024] * in_proj_w[4096,1024]^T
    {
        dim3 grid((2 * DI) / BN, ROWS / BM);
        sgemm_nt<<<grid, 256>>>(x, inw, xz, ROWS, 2 * DI, DMOD);
    }
    // 2. causal depthwise conv + silu
    conv_silu_kernel<<<(ROWS * DI) / 256, 256>>>(xz, convw, convb, u);
    // 3. dt path -> decay factors e
    dt_kernel<<<ROWS, 256>>>(u, xpw, dtw, dtb, alog, e);
    // 4. scan + skip + gate
    scan_kernel<<<(BB * DI) / 128, 128>>>(e, u, xz, Dvec, yg);
    // 5. out_proj: out[8192,1024] = yg[8192,2048] * out_proj_w[1024,2048]^T
    {
        dim3 grid(DMOD / BN, ROWS / BM);
        sgemm_nt<<<grid, 256>>>(yg, outw, out, ROWS, DMOD, DI);
    }
}

// round 3
// speedup vs baseline: 4.4725x; 4.4725x over previous
#include <cuda_runtime.h>
#include <math.h>
#include <stdint.h>

// ---------------------------------------------------------------------------
// Problem constants
// ---------------------------------------------------------------------------
#define BB 2
#define LL 4096
#define DMOD 1024
#define DI 2048
#define DTR 64
#define KC 4
#define ROWS (BB * LL)       // 8192
#define NCH 64               // scan chunks
#define LC (LL / NCH)        // 64

// ---------------------------------------------------------------------------
// Scratch (device globals; no allocation allowed)
// ---------------------------------------------------------------------------
__device__ float g_xz[(size_t)ROWS * 2 * DI];   // in_proj output (xi | z)
__device__ float g_u [(size_t)ROWS * DI];       // conv+silu output
__device__ float g_dtlow[(size_t)ROWS * DTR];   // dt_low
__device__ float g_e [(size_t)ROWS * DI];       // dpre then e (in place)
__device__ float g_yg[(size_t)ROWS * DI];       // gated scan output
__device__ float g_S [(size_t)BB * NCH * DI];   // per-chunk partial state
__device__ float g_P [(size_t)BB * NCH * DI];   // per-chunk decay product
__device__ float g_C [(size_t)BB * NCH * DI];   // per-chunk carry-in

// ---------------------------------------------------------------------------
// PTX helpers (generic ISA only: cp.async + mma.sync tf32 — sm_103-safe)
// ---------------------------------------------------------------------------
__device__ __forceinline__ uint32_t smem_u32(const void* p) {
    uint32_t a;
    asm("{ .reg .u64 t; cvta.to.shared.u64 t, %1; cvt.u32.u64 %0, t; }"
        : "=r"(a) : "l"(p));
    return a;
}
__device__ __forceinline__ void cp_async16(uint32_t dst, const void* src) {
    asm volatile("cp.async.cg.shared.global [%0], [%1], 16;"
                 :: "r"(dst), "l"(src) : "memory");
}
#define CP_COMMIT() asm volatile("cp.async.commit_group;" ::: "memory")
#define CP_WAIT(n)  asm volatile("cp.async.wait_group %0;" :: "n"(n) : "memory")

__device__ __forceinline__ uint32_t f2tf32(float f) {
    uint32_t r;
    asm("cvt.rna.tf32.f32 %0, %1;" : "=r"(r) : "f"(f));
    return r;
}
__device__ __forceinline__ void mma_tf32(float* c, const uint32_t* a, const uint32_t* b) {
    asm volatile(
        "mma.sync.aligned.m16n8k8.row.col.f32.tf32.tf32.f32 "
        "{%0,%1,%2,%3}, {%4,%5,%6,%7}, {%8,%9}, {%0,%1,%2,%3};"
        : "+f"(c[0]), "+f"(c[1]), "+f"(c[2]), "+f"(c[3])
        : "r"(a[0]), "r"(a[1]), "r"(a[2]), "r"(a[3]), "r"(b[0]), "r"(b[1]));
}

// ---------------------------------------------------------------------------
// tf32 tensor-core GEMM: C[M,N] = A[M,K] * B[N,K]^T  (row-major, both)
// BM=128, BN/WM/WN template. BK=32. 256 threads. cp.async double buffer.
// smem stride 36 floats -> conflict-free fragment loads (bank = 4*grp+qid).
// ---------------------------------------------------------------------------
#define GBK 32
#define SST 36   // smem row stride in floats

template <int BN, int WM, int WN>
__global__ __launch_bounds__(256)
void gemm_tf32(const float* __restrict__ A, const float* __restrict__ B,
               float* __restrict__ C, int M, int N, int K) {
    constexpr int MT = 128 / (WM * 16);   // m16 tiles per warp
    constexpr int NT = BN / (WN * 8);     // n8 tiles per warp
    constexpr int AF4 = (128 * 8) / 256;  // float4 loads per thread for A
    constexpr int BF4 = (BN * 8) / 256;   // for B

    extern __shared__ float smem[];
    float* As = smem;                       // [2][128*SST]
    float* Bs = smem + 2 * 128 * SST;       // [2][BN*SST]

    const int tid = threadIdx.x;
    const int wid = tid >> 5;
    const int lane = tid & 31;
    const int grp = lane >> 2;   // 0..7
    const int qid = lane & 3;    // 0..3
    const int wm = wid / WN;
    const int wn = wid % WN;

    const int bx = blockIdx.x, by = blockIdx.y;
    const float* Ag = A + (size_t)by * 128 * K;
    const float* Bg = B + (size_t)bx * BN * K;

    const uint32_t sA = smem_u32(As);
    const uint32_t sB = smem_u32(Bs);

    float acc[MT][NT][4];
    #pragma unroll
    for (int i = 0; i < MT; i++)
        #pragma unroll
        for (int j = 0; j < NT; j++)
            #pragma unroll
            for (int q = 0; q < 4; q++) acc[i][j][q] = 0.f;

    const int nK = K / GBK;

    // prologue: tile 0 -> buf 0
    {
        #pragma unroll
        for (int t = 0; t < AF4; t++) {
            int f4 = tid + t * 256;
            int row = f4 >> 3, c4 = f4 & 7;
            cp_async16(sA + (row * SST + c4 * 4) * 4, Ag + (size_t)row * K + c4 * 4);
        }
        #pragma unroll
        for (int t = 0; t < BF4; t++) {
            int f4 = tid + t * 256;
            int row = f4 >> 3, c4 = f4 & 7;
            cp_async16(sB + (row * SST + c4 * 4) * 4, Bg + (size_t)row * K + c4 * 4);
        }
        CP_COMMIT();
    }

    int buf = 0;
    for (int kt = 0; kt < nK; kt++) {
        if (kt + 1 < nK) {
            const uint32_t dA = sA + (buf ^ 1) * 128 * SST * 4;
            const uint32_t dB = sB + (buf ^ 1) * BN * SST * 4;
            const int koff = (kt + 1) * GBK;
            #pragma unroll
            for (int t = 0; t < AF4; t++) {
                int f4 = tid + t * 256;
                int row = f4 >> 3, c4 = f4 & 7;
                cp_async16(dA + (row * SST + c4 * 4) * 4, Ag + (size_t)row * K + koff + c4 * 4);
            }
            #pragma unroll
            for (int t = 0; t < BF4; t++) {
                int f4 = tid + t * 256;
                int row = f4 >> 3, c4 = f4 & 7;
                cp_async16(dB + (row * SST + c4 * 4) * 4, Bg + (size_t)row * K + koff + c4 * 4);
            }
            CP_COMMIT();
            CP_WAIT(1);
        } else {
            CP_WAIT(0);
        }
        __syncthreads();

        const float* Ab = As + buf * 128 * SST;
        const float* Bb = Bs + buf * BN * SST;

        #pragma unroll
        for (int s = 0; s < GBK / 8; s++) {
            const int kc0 = s * 8 + qid;
            uint32_t af[MT][4];
            #pragma unroll
            for (int mt = 0; mt < MT; mt++) {
                const int r0 = wm * (MT * 16) + mt * 16 + grp;
                af[mt][0] = f2tf32(Ab[r0 * SST + kc0]);
                af[mt][1] = f2tf32(Ab[(r0 + 8) * SST + kc0]);
                af[mt][2] = f2tf32(Ab[r0 * SST + kc0 + 4]);
                af[mt][3] = f2tf32(Ab[(r0 + 8) * SST + kc0 + 4]);
            }
            uint32_t bf[NT][2];
            #pragma unroll
            for (int nt = 0; nt < NT; nt++) {
                const int c0 = wn * (NT * 8) + nt * 8 + grp;
                bf[nt][0] = f2tf32(Bb[c0 * SST + kc0]);
                bf[nt][1] = f2tf32(Bb[c0 * SST + kc0 + 4]);
            }
            #pragma unroll
            for (int mt = 0; mt < MT; mt++)
                #pragma unroll
                for (int nt = 0; nt < NT; nt++)
                    mma_tf32(acc[mt][nt], af[mt], bf[nt]);
        }
        __syncthreads();
        buf ^= 1;
    }

    // epilogue
    #pragma unroll
    for (int mt = 0; mt < MT; mt++) {
        const int r0 = by * 128 + wm * (MT * 16) + mt * 16 + grp;
        #pragma unroll
        for (int nt = 0; nt < NT; nt++) {
            const int c0 = bx * BN + wn * (NT * 8) + nt * 8 + qid * 2;
            *(float2*)(C + (size_t)r0 * N + c0) = make_float2(acc[mt][nt][0], acc[mt][nt][1]);
            *(float2*)(C + (size_t)(r0 + 8) * N + c0) = make_float2(acc[mt][nt][2], acc[mt][nt][3]);
        }
    }
}

// ---------------------------------------------------------------------------
// Depthwise causal conv1d (K=4) + bias + SiLU
// ---------------------------------------------------------------------------
__global__ __launch_bounds__(256)
void conv_silu_kernel(const float* __restrict__ xz,
                      const float* __restrict__ cw,
                      const float* __restrict__ cb,
                      float* __restrict__ u) {
    int idx = blockIdx.x * blockDim.x + threadIdx.x;
    int d = idx & (DI - 1);
    int bl = idx / DI;
    int l = bl & (LL - 1);

    float acc = cb[d];
    #pragma unroll
    for (int k = 0; k < KC; k++) {
        int ls = l - (KC - 1) + k;
        if (ls >= 0)
            acc = fmaf(cw[d * KC + k], xz[(size_t)(bl - (KC - 1) + k) * (2 * DI) + d], acc);
    }
    u[idx] = acc / (1.f + expf(-acc));
}

// ---------------------------------------------------------------------------
// e = clip(exp(clip(softplus(dpre+b),1e-6,10) * clip(-exp(A_log),-10,-1e-6)),1e-6,1)
// ---------------------------------------------------------------------------
__global__ __launch_bounds__(256)
void e_kernel(float* __restrict__ dpre,
              const float* __restrict__ dtb,
              const float* __restrict__ alog) {
    int idx = blockIdx.x * blockDim.x + threadIdx.x;
    int d = idx & (DI - 1);
    float acc = dpre[idx] + dtb[d];
    float delta = (acc > 20.f) ? acc : log1pf(expf(acc));
    delta = fminf(fmaxf(delta, 1e-6f), 10.f);
    float A = fminf(fmaxf(-expf(alog[d]), -10.f), -1e-6f);
    float ev = expf(delta * A);
    dpre[idx] = fminf(fmaxf(ev, 1e-6f), 1.f);
}

// ---------------------------------------------------------------------------
// Chunked scan
// ---------------------------------------------------------------------------
__global__ __launch_bounds__(256)
void scan_pass1(const float* __restrict__ e, const float* __restrict__ u,
                float* __restrict__ S, float* __restrict__ P) {
    int gid = blockIdx.x * blockDim.x + threadIdx.x;   // BB*NCH*DI
    int d = gid & (DI - 1);
    int bc = gid / DI;
    int c = bc & (NCH - 1);
    int b = bc / NCH;
    size_t base = ((size_t)b * LL + (size_t)c * LC) * DI + d;
    float state = 0.f, prod = 1.f;
    #pragma unroll 4
    for (int l = 0; l < LC; l++) {
        float et = e[base + (size_t)l * DI];
        float ut = u[base + (size_t)l * DI];
        state = fminf(fmaxf(fmaf(state, et, ut), -1e4f), 1e4f);
        prod *= et;
    }
    S[gid] = state;
    P[gid] = prod;
}

__global__ __launch_bounds__(128)
void carry_kernel(const float* __restrict__ S, const float* __restrict__ P,
                  float* __restrict__ Cy) {
    int gid = blockIdx.x * blockDim.x + threadIdx.x;   // BB*DI
    int b = gid / DI, d = gid - b * DI;
    float cr = 0.f;
    for (int c = 0; c < NCH; c++) {
        size_t i = ((size_t)b * NCH + c) * DI + d;
        Cy[i] = cr;
        cr = fminf(fmaxf(fmaf(cr, P[i], S[i]), -1e4f), 1e4f);
    }
}

__global__ __launch_bounds__(256)
void scan_pass2(const float* __restrict__ e, const float* __restrict__ u,
                const float* __restrict__ xz, const float* __restrict__ Dvec,
                const float* __restrict__ Cy, float* __restrict__ yg) {
    int gid = blockIdx.x * blockDim.x + threadIdx.x;
    int d = gid & (DI - 1);
    int bc = gid / DI;
    int c = bc & (NCH - 1);
    int b = bc / NCH;
    size_t base  = ((size_t)b * LL + (size_t)c * LC) * DI + d;
    size_t zbase = ((size_t)b * LL + (size_t)c * LC) * (2 * DI) + DI + d;
    const float Dd = Dvec[d];
    float state = Cy[gid];
    #pragma unroll 4
    for (int l = 0; l < LC; l++) {
        float et = e[base + (size_t)l * DI];
        float ut = u[base + (size_t)l * DI];
        float zt = xz[zbase + (size_t)l * (2 * DI)];
        state = fminf(fmaxf(fmaf(state, et, ut), -1e4f), 1e4f);
        float y = fminf(fmaxf(fmaf(ut, Dd, state), -1e4f), 1e4f);
        float sg = zt / (1.f + expf(-zt));
        yg[base + (size_t)l * DI] = y * sg;
    }
}

// ---------------------------------------------------------------------------
// Launch
// ---------------------------------------------------------------------------
extern "C" void kernel_launch(void* const* d_in, const int* in_sizes, int n_in,
                              void* d_out, int out_size) {
    const float* x     = (const float*)d_in[0];
    const float* inw   = (const float*)d_in[1];
    const float* convw = (const float*)d_in[2];
    const float* convb = (const float*)d_in[3];
    const float* xpw   = (const float*)d_in[4];
    const float* dtw   = (const float*)d_in[5];
    const float* dtb   = (const float*)d_in[6];
    const float* alog  = (const float*)d_in[7];
    const float* Dvec  = (const float*)d_in[8];
    const float* outw  = (const float*)d_in[9];
    float* out = (float*)d_out;

    float *xz, *u, *dtlow, *e, *yg, *S, *P, *Cy;
    cudaGetSymbolAddress((void**)&xz, g_xz);
    cudaGetSymbolAddress((void**)&u, g_u);
    cudaGetSymbolAddress((void**)&dtlow, g_dtlow);
    cudaGetSymbolAddress((void**)&e, g_e);
    cudaGetSymbolAddress((void**)&yg, g_yg);
    cudaGetSymbolAddress((void**)&S, g_S);
    cudaGetSymbolAddress((void**)&P, g_P);
    cudaGetSymbolAddress((void**)&Cy, g_C);

    const int SM128 = 2 * (128 * SST + 128 * SST) * 4;  // 73728 B
    const int SM64  = 2 * (128 * SST + 64 * SST) * 4;   // 55296 B
    cudaFuncSetAttribute((const void*)gemm_tf32<128, 2, 4>,
                         cudaFuncAttributeMaxDynamicSharedMemorySize, SM128);
    cudaFuncSetAttribute((const void*)gemm_tf32<64, 4, 2>,
                         cudaFuncAttributeMaxDynamicSharedMemorySize, SM64);

    // 1. in_proj: xz[8192,4096] = x * inw^T   (K=1024)
    gemm_tf32<128, 2, 4><<<dim3((2 * DI) / 128, ROWS / 128), 256, SM128>>>(
        x, inw, xz, ROWS, 2 * DI, DMOD);
    // 2. conv + silu -> u
    conv_silu_kernel<<<(ROWS * DI) / 256, 256>>>(xz, convw, convb, u);
    // 3. dtlow[8192,64] = u * xpw^T   (K=2048)
    gemm_tf32<64, 4, 2><<<dim3(1, ROWS / 128), 256, SM64>>>(u, xpw, dtlow, ROWS, DTR, DI);
    // 4. dpre[8192,2048] = dtlow * dtw^T   (K=64)
    gemm_tf32<128, 2, 4><<<dim3(DI / 128, ROWS / 128), 256, SM128>>>(
        dtlow, dtw, e, ROWS, DI, DTR);
    // 5. e = f(dpre) in place
    e_kernel<<<(ROWS * DI) / 256, 256>>>(e, dtb, alog);
    // 6. chunked scan
    scan_pass1<<<(BB * NCH * DI) / 256, 256>>>(e, u, S, P);
    carry_kernel<<<(BB * DI) / 128, 128>>>(S, P, Cy);
    scan_pass2<<<(BB * NCH * DI) / 256, 256>>>(e, u, xz, Dvec, Cy, yg);
    // 7. out_proj: out[8192,1024] = yg * outw^T   (K=2048)
    gemm_tf32<128, 2, 4><<<dim3(DMOD / 128, ROWS / 128), 256, SM128>>>(
        yg, outw, out, ROWS, DMOD, DI);
}

// round 4
// speedup vs baseline: 5.3269x; 1.1911x over previous
#include <cuda_runtime.h>
#include <math.h>
#include <stdint.h>

// ---------------------------------------------------------------------------
// Problem constants
// ---------------------------------------------------------------------------
#define BB 2
#define LL 4096
#define DMOD 1024
#define DI 2048
#define DTR 64
#define KC 4
#define ROWS (BB * LL)       // 8192
#define NCH 64               // scan chunks
#define LC (LL / NCH)        // 64

// ---------------------------------------------------------------------------
// Scratch (device globals; no allocation allowed)
// ---------------------------------------------------------------------------
__device__ float g_xz[(size_t)ROWS * 2 * DI];   // in_proj output (xi | z)
__device__ float g_u [(size_t)ROWS * DI];       // conv+silu output
__device__ float g_dtlow[(size_t)ROWS * DTR];   // dt_low (tf32-rounded)
__device__ float g_e [(size_t)ROWS * DI];       // decay factors (fused epilogue)
__device__ float g_yg[(size_t)ROWS * DI];       // gated scan output (tf32-rounded)
__device__ float g_S [(size_t)BB * NCH * DI];
__device__ float g_P [(size_t)BB * NCH * DI];
__device__ float g_C [(size_t)BB * NCH * DI];
// tf32-pre-rounded GEMM operands
__device__ float g_xr  [(size_t)ROWS * DMOD];
__device__ float g_inwr[(size_t)2 * DI * DMOD];
__device__ float g_outwr[(size_t)DMOD * DI];
__device__ float g_xpwr[(size_t)DTR * DI];
__device__ float g_dtwr[(size_t)DI * DTR];

// ---------------------------------------------------------------------------
// PTX helpers (generic ISA: cp.async + mma.sync tf32 — sm_103-safe)
// ---------------------------------------------------------------------------
__device__ __forceinline__ uint32_t smem_u32(const void* p) {
    uint32_t a;
    asm("{ .reg .u64 t; cvta.to.shared.u64 t, %1; cvt.u32.u64 %0, t; }"
        : "=r"(a) : "l"(p));
    return a;
}
__device__ __forceinline__ void cp_async16(uint32_t dst, const void* src) {
    asm volatile("cp.async.cg.shared.global [%0], [%1], 16;"
                 :: "r"(dst), "l"(src) : "memory");
}
#define CP_COMMIT() asm volatile("cp.async.commit_group;" ::: "memory")
#define CP_WAIT(n)  asm volatile("cp.async.wait_group %0;" :: "n"(n) : "memory")

__device__ __forceinline__ uint32_t f2tf32(float f) {
    uint32_t r;
    asm("cvt.rna.tf32.f32 %0, %1;" : "=r"(r) : "f"(f));
    return r;
}
__device__ __forceinline__ void mma_tf32(float* c, const uint32_t* a, const uint32_t* b) {
    asm volatile(
        "mma.sync.aligned.m16n8k8.row.col.f32.tf32.tf32.f32 "
        "{%0,%1,%2,%3}, {%4,%5,%6,%7}, {%8,%9}, {%0,%1,%2,%3};"
        : "+f"(c[0]), "+f"(c[1]), "+f"(c[2]), "+f"(c[3])
        : "r"(a[0]), "r"(a[1]), "r"(a[2]), "r"(a[3]), "r"(b[0]), "r"(b[1]));
}

__device__ __forceinline__ float e_from_dpre(float acc, float bias, float al) {
    float v = acc + bias;
    float delta = (v > 20.f) ? v : log1pf(expf(v));
    delta = fminf(fmaxf(delta, 1e-6f), 10.f);
    float A = fminf(fmaxf(-expf(al), -10.f), -1e-6f);
    float ev = expf(delta * A);
    return fminf(fmaxf(ev, 1e-6f), 1.f);
}

// ---------------------------------------------------------------------------
// tf32 tensor-core GEMM: C[M,N] = A[M,K] * B[N,K]^T  (row-major both).
// BM=128, BN/WM/WN template, BK=32, 256 threads, cp.async double buffer.
// SST=40 floats (stride%32==8) -> conflict-free LDS.64 fragment loads.
// Fragment trick: load {mem[2q], mem[2q+1]} -> k-slots (q, q+4) on BOTH A and
// B sides; contraction is symmetric over k so any consistent layout is valid.
// CVTA: convert A fragments (A not pre-rounded). EPI: 0=plain, 1=round-store,
// 2=fused e (softplus/exp epilogue with vb1=dtb, vb2=A_log).
// ---------------------------------------------------------------------------
#define GBK 32
#define SST 40

template <int BN, int WM, int WN, bool CVTA, int EPI>
__global__ __launch_bounds__(256)
void gemm_tf32(const float* __restrict__ A, const float* __restrict__ B,
               float* __restrict__ C, int M, int N, int K,
               const float* __restrict__ vb1, const float* __restrict__ vb2) {
    constexpr int MT = 128 / (WM * 16);
    constexpr int NT = BN / (WN * 8);
    constexpr int AF4 = (128 * 8) / 256;
    constexpr int BF4 = (BN * 8) / 256;

    extern __shared__ float smem[];
    float* As = smem;                   // [2][128*SST]
    float* Bs = smem + 2 * 128 * SST;   // [2][BN*SST]

    const int tid = threadIdx.x;
    const int wid = tid >> 5;
    const int lane = tid & 31;
    const int grp = lane >> 2;
    const int qid = lane & 3;
    const int wm = wid / WN;
    const int wn = wid % WN;

    const int bx = blockIdx.x, by = blockIdx.y;
    const float* Ag = A + (size_t)by * 128 * K;
    const float* Bg = B + (size_t)bx * BN * K;

    const uint32_t sA = smem_u32(As);
    const uint32_t sB = smem_u32(Bs);

    float acc[MT][NT][4];
    #pragma unroll
    for (int i = 0; i < MT; i++)
        #pragma unroll
        for (int j = 0; j < NT; j++)
            #pragma unroll
            for (int q = 0; q < 4; q++) acc[i][j][q] = 0.f;

    const int nK = K / GBK;

    // prologue
    #pragma unroll
    for (int t = 0; t < AF4; t++) {
        int f4 = tid + t * 256;
        int row = f4 >> 3, c4 = f4 & 7;
        cp_async16(sA + (row * SST + c4 * 4) * 4, Ag + (size_t)row * K + c4 * 4);
    }
    #pragma unroll
    for (int t = 0; t < BF4; t++) {
        int f4 = tid + t * 256;
        int row = f4 >> 3, c4 = f4 & 7;
        cp_async16(sB + (row * SST + c4 * 4) * 4, Bg + (size_t)row * K + c4 * 4);
    }
    CP_COMMIT();

    int buf = 0;
    for (int kt = 0; kt < nK; kt++) {
        if (kt + 1 < nK) {
            const uint32_t dA = sA + (buf ^ 1) * 128 * SST * 4;
            const uint32_t dB = sB + (buf ^ 1) * BN * SST * 4;
            const int koff = (kt + 1) * GBK;
            #pragma unroll
            for (int t = 0; t < AF4; t++) {
                int f4 = tid + t * 256;
                int row = f4 >> 3, c4 = f4 & 7;
                cp_async16(dA + (row * SST + c4 * 4) * 4, Ag + (size_t)row * K + koff + c4 * 4);
            }
            #pragma unroll
            for (int t = 0; t < BF4; t++) {
                int f4 = tid + t * 256;
                int row = f4 >> 3, c4 = f4 & 7;
                cp_async16(dB + (row * SST + c4 * 4) * 4, Bg + (size_t)row * K + koff + c4 * 4);
            }
            CP_COMMIT();
            CP_WAIT(1);
        } else {
            CP_WAIT(0);
        }
        __syncthreads();

        const float* Ab = As + buf * 128 * SST;
        const float* Bb = Bs + buf * BN * SST;

        #pragma unroll
        for (int s = 0; s < GBK / 8; s++) {
            const int kc2 = s * 8 + 2 * qid;   // float2-aligned fragment column
            uint32_t af[MT][4];
            #pragma unroll
            for (int mt = 0; mt < MT; mt++) {
                const int r0 = wm * (MT * 16) + mt * 16 + grp;
                float2 v0 = *(const float2*)(Ab + r0 * SST + kc2);
                float2 v1 = *(const float2*)(Ab + (r0 + 8) * SST + kc2);
                if (CVTA) {
                    af[mt][0] = f2tf32(v0.x); af[mt][2] = f2tf32(v0.y);
                    af[mt][1] = f2tf32(v1.x); af[mt][3] = f2tf32(v1.y);
                } else {
                    af[mt][0] = __float_as_uint(v0.x); af[mt][2] = __float_as_uint(v0.y);
                    af[mt][1] = __float_as_uint(v1.x); af[mt][3] = __float_as_uint(v1.y);
                }
            }
            uint32_t bf[NT][2];
            #pragma unroll
            for (int nt = 0; nt < NT; nt++) {
                const int c0 = wn * (NT * 8) + nt * 8 + grp;
                float2 v = *(const float2*)(Bb + c0 * SST + kc2);
                bf[nt][0] = __float_as_uint(v.x);
                bf[nt][1] = __float_as_uint(v.y);
            }
            #pragma unroll
            for (int mt = 0; mt < MT; mt++)
                #pragma unroll
                for (int nt = 0; nt < NT; nt++)
                    mma_tf32(acc[mt][nt], af[mt], bf[nt]);
        }
        __syncthreads();
        buf ^= 1;
    }

    // epilogue
    #pragma unroll
    for (int mt = 0; mt < MT; mt++) {
        const int r0 = by * 128 + wm * (MT * 16) + mt * 16 + grp;
        #pragma unroll
        for (int nt = 0; nt < NT; nt++) {
            const int c0 = bx * BN + wn * (NT * 8) + nt * 8 + qid * 2;
            float o0 = acc[mt][nt][0], o1 = acc[mt][nt][1];
            float o2 = acc[mt][nt][2], o3 = acc[mt][nt][3];
            if (EPI == 1) {
                o0 = __uint_as_float(f2tf32(o0)); o1 = __uint_as_float(f2tf32(o1));
                o2 = __uint_as_float(f2tf32(o2)); o3 = __uint_as_float(f2tf32(o3));
            } else if (EPI == 2) {
                float2 bb = *(const float2*)(vb1 + c0);
                float2 aa = *(const float2*)(vb2 + c0);
                o0 = e_from_dpre(o0, bb.x, aa.x); o1 = e_from_dpre(o1, bb.y, aa.y);
                o2 = e_from_dpre(o2, bb.x, aa.x); o3 = e_from_dpre(o3, bb.y, aa.y);
            }
            *(float2*)(C + (size_t)r0 * N + c0) = make_float2(o0, o1);
            *(float2*)(C + (size_t)(r0 + 8) * N + c0) = make_float2(o2, o3);
        }
    }
}

// ---------------------------------------------------------------------------
// tf32 rounding prepass (vectorized)
// ---------------------------------------------------------------------------
__global__ __launch_bounds__(256)
void round_tf32_kernel(const float* __restrict__ in, float* __restrict__ out, int n4) {
    int i = blockIdx.x * blockDim.x + threadIdx.x;
    if (i < n4) {
        float4 v = ((const float4*)in)[i];
        v.x = __uint_as_float(f2tf32(v.x));
        v.y = __uint_as_float(f2tf32(v.y));
        v.z = __uint_as_float(f2tf32(v.z));
        v.w = __uint_as_float(f2tf32(v.w));
        ((float4*)out)[i] = v;
    }
}

// ---------------------------------------------------------------------------
// Depthwise causal conv1d (K=4) + bias + SiLU; 8 l-values per thread.
// ---------------------------------------------------------------------------
__global__ __launch_bounds__(256)
void conv_silu_kernel(const float* __restrict__ xz,
                      const float* __restrict__ cw,
                      const float* __restrict__ cb,
                      float* __restrict__ u) {
    int idx = blockIdx.x * blockDim.x + threadIdx.x;   // DI * ROWS/8
    int d = idx & (DI - 1);
    int g = idx >> 11;
    int l0 = (g & (LL / 8 - 1)) * 8;
    int b = g >> 9;
    size_t bl0 = (size_t)b * LL + l0;

    float w0 = cw[d * KC], w1 = cw[d * KC + 1], w2 = cw[d * KC + 2], w3 = cw[d * KC + 3];
    float bias = cb[d];

    float xm3 = 0.f, xm2 = 0.f, xm1 = 0.f;
    if (l0 > 0) {
        xm3 = xz[(bl0 - 3) * (2 * DI) + d];
        xm2 = xz[(bl0 - 2) * (2 * DI) + d];
        xm1 = xz[(bl0 - 1) * (2 * DI) + d];
    }
    #pragma unroll
    for (int j = 0; j < 8; j++) {
        float xc = xz[(bl0 + j) * (2 * DI) + d];
        float acc = bias;
        acc = fmaf(w0, xm3, acc);
        acc = fmaf(w1, xm2, acc);
        acc = fmaf(w2, xm1, acc);
        acc = fmaf(w3, xc, acc);
        u[(bl0 + j) * DI + d] = acc / (1.f + expf(-acc));
        xm3 = xm2; xm2 = xm1; xm1 = xc;
    }
}

// ---------------------------------------------------------------------------
// Chunked scan
// ---------------------------------------------------------------------------
__global__ __launch_bounds__(256)
void scan_pass1(const float* __restrict__ e, const float* __restrict__ u,
                float* __restrict__ S, float* __restrict__ P) {
    int gid = blockIdx.x * blockDim.x + threadIdx.x;
    int d = gid & (DI - 1);
    int bc = gid / DI;
    int c = bc & (NCH - 1);
    int b = bc / NCH;
    size_t base = ((size_t)b * LL + (size_t)c * LC) * DI + d;
    float state = 0.f, prod = 1.f;
    #pragma unroll 4
    for (int l = 0; l < LC; l++) {
        float et = e[base + (size_t)l * DI];
        float ut = u[base + (size_t)l * DI];
        state = fminf(fmaxf(fmaf(state, et, ut), -1e4f), 1e4f);
        prod *= et;
    }
    S[gid] = state;
    P[gid] = prod;
}

__global__ __launch_bounds__(128)
void carry_kernel(const float* __restrict__ S, const float* __restrict__ P,
                  float* __restrict__ Cy) {
    int gid = blockIdx.x * blockDim.x + threadIdx.x;
    int b = gid / DI, d = gid - b * DI;
    float cr = 0.f;
    for (int c = 0; c < NCH; c++) {
        size_t i = ((size_t)b * NCH + c) * DI + d;
        Cy[i] = cr;
        cr = fminf(fmaxf(fmaf(cr, P[i], S[i]), -1e4f), 1e4f);
    }
}

__global__ __launch_bounds__(256)
void scan_pass2(const float* __restrict__ e, const float* __restrict__ u,
                const float* __restrict__ xz, const float* __restrict__ Dvec,
                const float* __restrict__ Cy, float* __restrict__ yg) {
    int gid = blockIdx.x * blockDim.x + threadIdx.x;
    int d = gid & (DI - 1);
    int bc = gid / DI;
    int c = bc & (NCH - 1);
    int b = bc / NCH;
    size_t base  = ((size_t)b * LL + (size_t)c * LC) * DI + d;
    size_t zbase = ((size_t)b * LL + (size_t)c * LC) * (2 * DI) + DI + d;
    const float Dd = Dvec[d];
    float state = Cy[gid];
    #pragma unroll 4
    for (int l = 0; l < LC; l++) {
        float et = e[base + (size_t)l * DI];
        float ut = u[base + (size_t)l * DI];
        float zt = xz[zbase + (size_t)l * (2 * DI)];
        state = fminf(fmaxf(fmaf(state, et, ut), -1e4f), 1e4f);
        float y = fminf(fmaxf(fmaf(ut, Dd, state), -1e4f), 1e4f);
        float sg = zt / (1.f + expf(-zt));
        // tf32-round: yg feeds only out_proj GEMM
        yg[base + (size_t)l * DI] = __uint_as_float(f2tf32(y * sg));
    }
}

// ---------------------------------------------------------------------------
// Launch
// ---------------------------------------------------------------------------
extern "C" void kernel_launch(void* const* d_in, const int* in_sizes, int n_in,
                              void* d_out, int out_size) {
    const float* x     = (const float*)d_in[0];
    const float* inw   = (const float*)d_in[1];
    const float* convw = (const float*)d_in[2];
    const float* convb = (const float*)d_in[3];
    const float* xpw   = (const float*)d_in[4];
    const float* dtw   = (const float*)d_in[5];
    const float* dtb   = (const float*)d_in[6];
    const float* alog  = (const float*)d_in[7];
    const float* Dvec  = (const float*)d_in[8];
    const float* outw  = (const float*)d_in[9];
    float* out = (float*)d_out;

    float *xz, *u, *dtlow, *e, *yg, *S, *P, *Cy;
    float *xr, *inwr, *outwr, *xpwr, *dtwr;
    cudaGetSymbolAddress((void**)&xz, g_xz);
    cudaGetSymbolAddress((void**)&u, g_u);
    cudaGetSymbolAddress((void**)&dtlow, g_dtlow);
    cudaGetSymbolAddress((void**)&e, g_e);
    cudaGetSymbolAddress((void**)&yg, g_yg);
    cudaGetSymbolAddress((void**)&S, g_S);
    cudaGetSymbolAddress((void**)&P, g_P);
    cudaGetSymbolAddress((void**)&Cy, g_C);
    cudaGetSymbolAddress((void**)&xr, g_xr);
    cudaGetSymbolAddress((void**)&inwr, g_inwr);
    cudaGetSymbolAddress((void**)&outwr, g_outwr);
    cudaGetSymbolAddress((void**)&xpwr, g_xpwr);
    cudaGetSymbolAddress((void**)&dtwr, g_dtwr);

    const int SM128 = 2 * (128 * SST + 128 * SST) * 4;  // 81920 B
    const int SM64  = 2 * (128 * SST + 64 * SST) * 4;   // 61440 B
    cudaFuncSetAttribute((const void*)gemm_tf32<128, 2, 4, false, 0>,
                         cudaFuncAttributeMaxDynamicSharedMemorySize, SM128);
    cudaFuncSetAttribute((const void*)gemm_tf32<128, 2, 4, false, 2>,
                         cudaFuncAttributeMaxDynamicSharedMemorySize, SM128);
    cudaFuncSetAttribute((const void*)gemm_tf32<64, 4, 2, true, 1>,
                         cudaFuncAttributeMaxDynamicSharedMemorySize, SM64);

    // 0. tf32 rounding prepasses
    round_tf32_kernel<<<(ROWS * DMOD / 4 + 255) / 256, 256>>>(x, xr, ROWS * DMOD / 4);
    round_tf32_kernel<<<(2 * DI * DMOD / 4 + 255) / 256, 256>>>(inw, inwr, 2 * DI * DMOD / 4);
    round_tf32_kernel<<<(DMOD * DI / 4 + 255) / 256, 256>>>(outw, outwr, DMOD * DI / 4);
    round_tf32_kernel<<<(DTR * DI / 4 + 255) / 256, 256>>>(xpw, xpwr, DTR * DI / 4);
    round_tf32_kernel<<<(DI * DTR / 4 + 255) / 256, 256>>>(dtw, dtwr, DI * DTR / 4);

    // 1. in_proj: xz[8192,4096] = xr * inwr^T   (K=1024)
    gemm_tf32<128, 2, 4, false, 0><<<dim3((2 * DI) / 128, ROWS / 128), 256, SM128>>>(
        xr, inwr, xz, ROWS, 2 * DI, DMOD, nullptr, nullptr);
    // 2. conv + silu -> u
    conv_silu_kernel<<<(ROWS / 8) * DI / 256, 256>>>(xz, convw, convb, u);
    // 3. dtlow[8192,64] = u * xpwr^T (K=2048); round output
    gemm_tf32<64, 4, 2, true, 1><<<dim3(1, ROWS / 128), 256, SM64>>>(
        u, xpwr, dtlow, ROWS, DTR, DI, nullptr, nullptr);
    // 4. e[8192,2048] = f(dtlow * dtwr^T + dtb)  (K=64, fused e epilogue)
    gemm_tf32<128, 2, 4, false, 2><<<dim3(DI / 128, ROWS / 128), 256, SM128>>>(
        dtlow, dtwr, e, ROWS, DI, DTR, dtb, alog);
    // 5. chunked scan
    scan_pass1<<<(BB * NCH * DI) / 256, 256>>>(e, u, S, P);
    carry_kernel<<<(BB * DI) / 128, 128>>>(S, P, Cy);
    scan_pass2<<<(BB * NCH * DI) / 256, 256>>>(e, u, xz, Dvec, Cy, yg);
    // 6. out_proj: out[8192,1024] = yg * outwr^T  (K=2048)
    gemm_tf32<128, 2, 4, false, 0><<<dim3(DMOD / 128, ROWS / 128), 256, SM128>>>(
        yg, outwr, out, ROWS, DMOD, DI, nullptr, nullptr);
}